// round 12
// baseline (speedup 1.0000x reference)
#include <cuda_runtime.h>
#include <cuda_bf16.h>
#include <math.h>

// Problem shape (fixed by reference setup_inputs)
#define B_    2
#define N_    4096
#define L_    512
#define TPB   128
#define KQ    2
#define QC    256           // queries per block (KQ*TPB)
#define NQ    16            // query chunks
#define MCH   64            // m points per block
#define NMC   64            // m chunks
#define TILE  32            // m points per smem tile
#define NPH   2             // phases per block (MCH/TILE)
#define SCW   132           // scol row width (4 parts x 33)
#define PTTP_BLKS (NQ*NMC)  // 1024
#define PPS_BLKS  544       // upper-triangle (q,mc) pairs: sum_q (64-4q), q<16
#define XBLKS     (PTTP_BLKS + PPS_BLKS)  // 1568 -> 3136 blocks total
#define RTOT      96        // reduce blocks (32 x 3)
#define FINF 3.4e38f

// Scratch (allocation-free: __device__ globals)
__device__ float        g_rowPT[B_ * NMC * N_];  // 2 MB
__device__ float        g_colTP[B_ * NQ  * N_];  // 512 KB
__device__ float        g_rowPP[B_ * NMC * N_];  // only mc >= 4*qc slots valid
__device__ float        g_colPP[B_ * NQ  * N_];  // only q <= qc slots valid
__device__ double       g_acc[6];    // [0]=PT+TP, [1,2]=PP s/s2 b0, [3,4]=b1, [5]=KL
__device__ unsigned int g_count;

// ---- f32x2 packed helpers -------------------------------------------------
static __device__ __forceinline__ unsigned long long pk2(float lo, float hi) {
    unsigned long long r;
    asm("mov.b64 %0, {%1,%2};" : "=l"(r) : "f"(lo), "f"(hi));
    return r;
}
static __device__ __forceinline__ unsigned long long fma2(
        unsigned long long a, unsigned long long b, unsigned long long c) {
    unsigned long long d;
    asm("fma.rn.f32x2 %0, %1, %2, %3;" : "=l"(d) : "l"(a), "l"(b), "l"(c));
    return d;
}
static __device__ __forceinline__ unsigned long long add2(
        unsigned long long a, unsigned long long b) {
    unsigned long long d;
    asm("add.rn.f32x2 %0, %1, %2;" : "=l"(d) : "l"(a), "l"(b));
    return d;
}
static __device__ __forceinline__ void upk2(unsigned long long v, float& lo, float& hi) {
    asm("mov.b64 {%0,%1}, %2;" : "=f"(lo), "=f"(hi) : "l"(v));
}

// ---- kernel 1: all pairwise-min work ---------------------------------------
// x < 1024: fused PT/TP block (q = x>>6 of pred, zc = x&63 m-chunk of target)
// x >= 1024: PP upper-triangle block (q, mc) with mc >= 4q, self-masked on diag
// 12 blocks/SM (forced): 48 warps/SM to cover LDS->FMA2 chains.
__global__ void __launch_bounds__(TPB, 12) pairmin_all(const float* __restrict__ pred,
                                                       const float* __restrict__ target) {
    __shared__ unsigned long long sd[TILE][4];
    __shared__ float scol[TILE * SCW];

    const int t = threadIdx.x;
    const int b = blockIdx.y;
    const int x = blockIdx.x;

    const float* A; const float* P;
    float* rowdst; float* coldst;
    int q, mbase; bool selfpass;
    if (x < PTTP_BLKS) {
        q = x >> 6; const int zc = x & 63;
        mbase = zc * MCH;
        A = pred; P = target; selfpass = false;
        rowdst = g_rowPT + (size_t)(b * NMC + zc) * N_;
        coldst = g_colTP + (size_t)(b * NQ + q) * N_;
    } else {
        int s = x - PTTP_BLKS; q = 0; int cnt = NMC;
        while (s >= cnt) { s -= cnt; q++; cnt -= 4; }
        const int mc = 4 * q + s;
        mbase = mc * MCH;
        A = pred; P = pred; selfpass = true;
        rowdst = g_rowPP + (size_t)(b * NMC + mc) * N_;
        coldst = g_colPP + (size_t)(b * NQ + q) * N_;
    }
    const int qbase = q * QC;
    const int qi0   = qbase + t;     // queries at qi0 and qi0 + TPB

    unsigned long long px2, py2, pz2, pp2;
    float mn0 = FINF, mn1 = FINF;
    {
        const float* a0 = A + (size_t)(b * N_ + qi0) * 3;
        const float* a1 = A + (size_t)(b * N_ + qi0 + TPB) * 3;
        float x0 = a0[0], y0 = a0[1], z0 = a0[2];
        float x1 = a1[0], y1 = a1[1], z1 = a1[2];
        px2 = pk2(x0, x1); py2 = pk2(y0, y1); pz2 = pk2(z0, z1);
        pp2 = pk2(fmaf(x0, x0, fmaf(y0, y0, z0 * z0)),
                  fmaf(x1, x1, fmaf(y1, y1, z1 * z1)));
    }

#pragma unroll
    for (int ph = 0; ph < NPH; ph++) {
        const int m0 = mbase + ph * TILE;
        __syncthreads();
        if (t < TILE) {
            const float* p = P + (size_t)(b * N_ + m0 + t) * 3;
            float xx = p[0], yy = p[1], zz = p[2];
            sd[t][0] = pk2(-2.f * xx, -2.f * xx);
            sd[t][1] = pk2(-2.f * yy, -2.f * yy);
            sd[t][2] = pk2(-2.f * zz, -2.f * zz);
            float ss = fmaf(xx, xx, fmaf(yy, yy, zz * zz));
            sd[t][3] = pk2(ss, ss);
        }
        __syncthreads();

        const int scbase = (t >> 5) * 33 + (t & 31);
        const bool dg = selfpass && (m0 < qbase + QC) && (m0 + TILE > qbase);
        if (!dg) {
#pragma unroll 8
            for (int j = 0; j < TILE; j++) {
                const ulonglong2 v01 = *reinterpret_cast<const ulonglong2*>(&sd[j][0]);
                const ulonglong2 v23 = *reinterpret_cast<const ulonglong2*>(&sd[j][2]);
                unsigned long long e = add2(v23.y, pp2);    // ss + pp
                e = fma2(pz2, v23.x, e);
                e = fma2(py2, v01.y, e);
                e = fma2(px2, v01.x, e);                    // = packed d
                float d0, d1; upk2(e, d0, d1);
                mn0 = fminf(mn0, d0);
                mn1 = fminf(mn1, d1);
                scol[j * SCW + scbase] = fminf(d0, d1);
            }
        } else {
#pragma unroll 4
            for (int j = 0; j < TILE; j++) {
                const ulonglong2 v01 = *reinterpret_cast<const ulonglong2*>(&sd[j][0]);
                const ulonglong2 v23 = *reinterpret_cast<const ulonglong2*>(&sd[j][2]);
                const int m = m0 + j;
                unsigned long long e = add2(v23.y, pp2);
                e = fma2(pz2, v23.x, e);
                e = fma2(py2, v01.y, e);
                e = fma2(px2, v01.x, e);
                float d0, d1; upk2(e, d0, d1);
                if (m == qi0)       d0 = FINF;              // self mask
                if (m == qi0 + TPB) d1 = FINF;
                mn0 = fminf(mn0, d0);
                mn1 = fminf(mn1, d1);
                scol[j * SCW + scbase] = fminf(d0, d1);
            }
        }
        __syncthreads();

        // fold: thread t -> (m = t>>2, part = t&3); bank = lane -> conflict-free
        const int mloc = t >> 2, part = t & 3;
        const float* src = scol + mloc * SCW + part * 33;
        float v = src[0];
#pragma unroll
        for (int i = 1; i < 32; i++) v = fminf(v, src[i]);
        v = fminf(v, __shfl_down_sync(0xffffffffu, v, 2, 4));
        v = fminf(v, __shfl_down_sync(0xffffffffu, v, 1, 4));
        if (part == 0) coldst[m0 + mloc] = v;
    }

    rowdst[qi0]       = mn0;
    rowdst[qi0 + TPB] = mn1;
}

// ---- kernel 2: reduce + KL + finalize (counter pattern, self-resetting) ----
// grid (32, 3): y=0 PT rows (depth 64), y=1 TP cols (depth 16) + KL in x==0,
// y=2 PP (rows mc in [4qc,64) + cols q in [0,qc]), qc = i>>8.
__global__ void __launch_bounds__(256) reduce_final(const float* __restrict__ mu,
                                                    const float* __restrict__ logvar,
                                                    float* __restrict__ out,
                                                    int out_size) {
    __shared__ double s1s[8], s2s[8], sks[8];
    __shared__ bool last;

    const int t = threadIdx.x, x = blockIdx.x, y = blockIdx.y;
    const int g = x * 256 + t;
    const int b = g >> 12;
    const int i = g & (N_ - 1);

    float v = FINF;
    double d2v = 0.0;
    if (y == 0) {
        const float* p = g_rowPT + (size_t)b * NMC * N_ + i;
#pragma unroll
        for (int s = 0; s < NMC; s++) v = fminf(v, p[(size_t)s * N_]);
    } else if (y == 1) {
        const float* p = g_colTP + (size_t)b * NQ * N_ + i;
#pragma unroll
        for (int s = 0; s < NQ; s++) v = fminf(v, p[(size_t)s * N_]);
    } else {
        const int qc = i >> 8;   // uniform within block (256-aligned chunks)
        const float* pr = g_rowPP + (size_t)b * NMC * N_ + i;
        for (int mc = 4 * qc; mc < NMC; mc++) v = fminf(v, pr[(size_t)mc * N_]);
        const float* pc = g_colPP + (size_t)b * NQ * N_ + i;
        for (int qq = 0; qq <= qc; qq++) v = fminf(v, pc[(size_t)qq * N_]);
        d2v = (double)v * (double)v;
    }
    double d1 = (double)v;

    double kls = 0.0;
    if (y == 1 && x == 0) {
        for (int idx = t; idx < B_ * L_; idx += 256) {
            double m  = (double)mu[idx];
            double lv = (double)logvar[idx];
            kls += 1.0 + lv - m * m - exp(lv);
        }
    }

#pragma unroll
    for (int o = 16; o > 0; o >>= 1) {
        d1  += __shfl_down_sync(0xffffffffu, d1,  o);
        d2v += __shfl_down_sync(0xffffffffu, d2v, o);
        kls += __shfl_down_sync(0xffffffffu, kls, o);
    }
    if ((t & 31) == 0) { s1s[t >> 5] = d1; s2s[t >> 5] = d2v; sks[t >> 5] = kls; }
    __syncthreads();

    if (t == 0) {
        double S1 = 0.0, S2 = 0.0, SK = 0.0;
#pragma unroll
        for (int w = 0; w < 8; w++) { S1 += s1s[w]; S2 += s2s[w]; SK += sks[w]; }
        if (y < 2) {
            atomicAdd(&g_acc[0], S1);
        } else {
            atomicAdd(&g_acc[1 + 2 * b], S1);
            atomicAdd(&g_acc[2 + 2 * b], S2);
        }
        if (y == 1 && x == 0) atomicAdd(&g_acc[5], SK);
        __threadfence();
        unsigned int n = atomicAdd(&g_count, 1u);
        last = (n == RTOT - 1);
    }
    __syncthreads();

    if (last && t == 0) {
        __threadfence();
        volatile double* acc = g_acc;
        double cd = acc[0] / (double)(B_ * N_);
        double dens = 0.0;
        for (int bb = 0; bb < B_; bb++) {
            double su  = acc[1 + 2 * bb];
            double su2 = acc[2 + 2 * bb];
            double var = (su2 - su * su / (double)N_) / (double)(N_ - 1);
            dens += sqrt(var > 0.0 ? var : 0.0);
        }
        dens /= (double)B_;
        double kl = -0.5 * acc[5] / (double)(B_ * L_);
        double total = cd + 0.001 * kl + 0.1 * dens;

        if (out_size > 0) out[0] = (float)total;
        if (out_size > 1) out[1] = (float)cd;
        if (out_size > 2) out[2] = (float)kl;
        if (out_size > 3) out[3] = (float)dens;

        // reset for next graph replay
        for (int k = 0; k < 6; k++) g_acc[k] = 0.0;
        __threadfence();
        g_count = 0u;
    }
}

extern "C" void kernel_launch(void* const* d_in, const int* in_sizes, int n_in,
                              void* d_out, int out_size) {
    const float* pred   = (const float*)d_in[0];
    const float* target = (const float*)d_in[1];
    const float* mu     = (const float*)d_in[2];
    const float* logvar = (const float*)d_in[3];
    float* out = (float*)d_out;

    pairmin_all<<<dim3(XBLKS, B_), TPB>>>(pred, target);
    reduce_final<<<dim3(32, 3), 256>>>(mu, logvar, out, out_size);
}

// round 13
// speedup vs baseline: 1.1263x; 1.1263x over previous
#include <cuda_runtime.h>
#include <cuda_bf16.h>
#include <math.h>

// Problem shape (fixed by reference setup_inputs)
#define B_    2
#define N_    4096
#define L_    512
#define TPB   128
#define KQ    4
#define KP    2
#define QC    512           // queries per block (KQ*TPB)
#define NQ    8             // query chunks
#define MCH   32            // m points per block (== TILE, single phase)
#define NMC   128           // m chunks
#define TILE  32
#define PTTP_BLKS (NQ*NMC)  // 1024
#define PPS_BLKS  576       // upper-triangle (q,mc) pairs: sum_q (128-16q)
#define XBLKS     (PTTP_BLKS + PPS_BLKS)  // 1600 -> 3200 blocks total
#define RTOT      96        // reduce blocks (32 x 3)
#define FINF 3.4e38f

// Scratch (allocation-free: __device__ globals)
__device__ float        g_rowPT[B_ * NMC * N_];  // 4 MB
__device__ float        g_colTP[B_ * NQ  * N_];
__device__ float        g_rowPP[B_ * NMC * N_];  // only mc >= 16*qc slots valid
__device__ float        g_colPP[B_ * NQ  * N_];  // only q <= qc slots valid
__device__ double       g_acc[6];    // [0]=PT+TP, [1,2]=PP s/s2 b0, [3,4]=b1, [5]=KL
__device__ unsigned int g_count;

// ---- f32x2 packed helpers -------------------------------------------------
static __device__ __forceinline__ unsigned long long pk2(float lo, float hi) {
    unsigned long long r;
    asm("mov.b64 %0, {%1,%2};" : "=l"(r) : "f"(lo), "f"(hi));
    return r;
}
static __device__ __forceinline__ unsigned long long fma2(
        unsigned long long a, unsigned long long b, unsigned long long c) {
    unsigned long long d;
    asm("fma.rn.f32x2 %0, %1, %2, %3;" : "=l"(d) : "l"(a), "l"(b), "l"(c));
    return d;
}
static __device__ __forceinline__ unsigned long long add2(
        unsigned long long a, unsigned long long b) {
    unsigned long long d;
    asm("add.rn.f32x2 %0, %1, %2;" : "=l"(d) : "l"(a), "l"(b));
    return d;
}
static __device__ __forceinline__ void upk2(unsigned long long v, float& lo, float& hi) {
    asm("mov.b64 {%0,%1}, %2;" : "=f"(lo), "=f"(hi) : "l"(v));
}

// ---- kernel 1: all pairwise-min work ---------------------------------------
// x < 1024: fused PT/TP block (q = x>>7 of pred, zc = x&127 m-chunk of target)
// x >= 1024: PP upper-triangle block (q, mc) with mc >= 16q, masked on diag
// Single 32-point tile per block; col-min via REDUX.MIN.U32 (d >= 0 so uint
// order == float order) -> no per-j STS, no serial 32-deep fold chain.
__global__ void __launch_bounds__(TPB) pairmin_all(const float* __restrict__ pred,
                                                   const float* __restrict__ target) {
    __shared__ unsigned long long sd[TILE][4];
    __shared__ float scol2[TILE][5];   // [m][warp] cross-warp partials (+pad)

    const int t = threadIdx.x;
    const int b = blockIdx.y;
    const int x = blockIdx.x;
    const int w = t >> 5, lane = t & 31;

    const float* A; const float* P;
    float* rowdst; float* coldst;
    int q, m0; bool selfpass;
    if (x < PTTP_BLKS) {
        q = x >> 7; const int zc = x & 127;
        m0 = zc * MCH;
        A = pred; P = target; selfpass = false;
        rowdst = g_rowPT + (size_t)(b * NMC + zc) * N_;
        coldst = g_colTP + (size_t)(b * NQ + q) * N_;
    } else {
        int s = x - PTTP_BLKS; q = 0; int cnt = NMC;
        while (s >= cnt) { s -= cnt; q++; cnt -= 16; }
        const int mc = 16 * q + s;
        m0 = mc * MCH;
        A = pred; P = pred; selfpass = true;
        rowdst = g_rowPP + (size_t)(b * NMC + mc) * N_;
        coldst = g_colPP + (size_t)(b * NQ + q) * N_;
    }
    const int qbase = q * QC;
    const int qi0   = qbase + t;   // query k lives at qi0 + k*TPB

    // stage tile (pair-duplicated packed form)
    if (t < TILE) {
        const float* p = P + (size_t)(b * N_ + m0 + t) * 3;
        float xx = p[0], yy = p[1], zz = p[2];
        sd[t][0] = pk2(-2.f * xx, -2.f * xx);
        sd[t][1] = pk2(-2.f * yy, -2.f * yy);
        sd[t][2] = pk2(-2.f * zz, -2.f * zz);
        float ss = fmaf(xx, xx, fmaf(yy, yy, zz * zz));
        sd[t][3] = pk2(ss, ss);
    }

    unsigned long long px2[KP], py2[KP], pz2[KP], pp2[KP];
    float mn[KQ];
#pragma unroll
    for (int kp = 0; kp < KP; kp++) {
        const float* a0 = A + (size_t)(b * N_ + qi0 + (2 * kp)     * TPB) * 3;
        const float* a1 = A + (size_t)(b * N_ + qi0 + (2 * kp + 1) * TPB) * 3;
        float x0 = a0[0], y0 = a0[1], z0 = a0[2];
        float x1 = a1[0], y1 = a1[1], z1 = a1[2];
        px2[kp] = pk2(x0, x1); py2[kp] = pk2(y0, y1); pz2[kp] = pk2(z0, z1);
        pp2[kp] = pk2(fmaf(x0, x0, fmaf(y0, y0, z0 * z0)),
                      fmaf(x1, x1, fmaf(y1, y1, z1 * z1)));
        mn[2 * kp] = FINF; mn[2 * kp + 1] = FINF;
    }
    __syncthreads();

    const bool dg = selfpass && (m0 >= qbase) && (m0 < qbase + QC);
    if (!dg) {
#pragma unroll 8
        for (int j = 0; j < TILE; j++) {
            const ulonglong2 v01 = *reinterpret_cast<const ulonglong2*>(&sd[j][0]);
            const ulonglong2 v23 = *reinterpret_cast<const ulonglong2*>(&sd[j][2]);
            float cm = FINF;
#pragma unroll
            for (int kp = 0; kp < KP; kp++) {
                unsigned long long e = add2(v23.y, pp2[kp]);   // ss + pp
                e = fma2(pz2[kp], v23.x, e);
                e = fma2(py2[kp], v01.y, e);
                e = fma2(px2[kp], v01.x, e);                   // = packed d
                float d0, d1; upk2(e, d0, d1);
                mn[2 * kp]     = fminf(mn[2 * kp],     d0);
                mn[2 * kp + 1] = fminf(mn[2 * kp + 1], d1);
                cm = fminf(cm, fminf(d0, d1));
            }
            unsigned int cu = __reduce_min_sync(0xffffffffu, __float_as_uint(cm));
            if (lane == 0) scol2[j][w] = __uint_as_float(cu);
        }
    } else {
#pragma unroll 4
        for (int j = 0; j < TILE; j++) {
            const ulonglong2 v01 = *reinterpret_cast<const ulonglong2*>(&sd[j][0]);
            const ulonglong2 v23 = *reinterpret_cast<const ulonglong2*>(&sd[j][2]);
            const int m = m0 + j;
            float cm = FINF;
#pragma unroll
            for (int kp = 0; kp < KP; kp++) {
                unsigned long long e = add2(v23.y, pp2[kp]);
                e = fma2(pz2[kp], v23.x, e);
                e = fma2(py2[kp], v01.y, e);
                e = fma2(px2[kp], v01.x, e);
                float d0, d1; upk2(e, d0, d1);
                if (m == qi0 + (2 * kp)     * TPB) d0 = FINF;  // self mask
                if (m == qi0 + (2 * kp + 1) * TPB) d1 = FINF;
                mn[2 * kp]     = fminf(mn[2 * kp],     d0);
                mn[2 * kp + 1] = fminf(mn[2 * kp + 1], d1);
                cm = fminf(cm, fminf(d0, d1));
            }
            unsigned int cu = __reduce_min_sync(0xffffffffu, __float_as_uint(cm));
            if (lane == 0) scol2[j][w] = __uint_as_float(cu);
        }
    }
    __syncthreads();

    // tiny fold: 32 threads combine 4 warp partials per m
    if (t < TILE) {
        float v = fminf(fminf(scol2[t][0], scol2[t][1]),
                        fminf(scol2[t][2], scol2[t][3]));
        coldst[m0 + t] = v;
    }

#pragma unroll
    for (int k = 0; k < KQ; k++) rowdst[qi0 + k * TPB] = mn[k];
}

// ---- kernel 2: reduce + KL + finalize (counter pattern, self-resetting) ----
// grid (32, 3): y=0 PT rows (depth 128), y=1 TP cols (depth 8) + KL in x==0,
// y=2 PP (rows mc in [16qc,128) + cols q in [0,qc]), qc = i>>9.
__global__ void __launch_bounds__(256) reduce_final(const float* __restrict__ mu,
                                                    const float* __restrict__ logvar,
                                                    float* __restrict__ out,
                                                    int out_size) {
    __shared__ double s1s[8], s2s[8], sks[8];
    __shared__ bool last;

    const int t = threadIdx.x, x = blockIdx.x, y = blockIdx.y;
    const int g = x * 256 + t;
    const int b = g >> 12;
    const int i = g & (N_ - 1);

    float v = FINF;
    double d2v = 0.0;
    if (y == 0) {
        const float* p = g_rowPT + (size_t)b * NMC * N_ + i;
#pragma unroll 16
        for (int s = 0; s < NMC; s++) v = fminf(v, p[(size_t)s * N_]);
    } else if (y == 1) {
        const float* p = g_colTP + (size_t)b * NQ * N_ + i;
#pragma unroll
        for (int s = 0; s < NQ; s++) v = fminf(v, p[(size_t)s * N_]);
    } else {
        const int qc = i >> 9;   // uniform within block (256-aligned chunks)
        const float* pr = g_rowPP + (size_t)b * NMC * N_ + i;
        for (int mc = 16 * qc; mc < NMC; mc++) v = fminf(v, pr[(size_t)mc * N_]);
        const float* pc = g_colPP + (size_t)b * NQ * N_ + i;
        for (int qq = 0; qq <= qc; qq++) v = fminf(v, pc[(size_t)qq * N_]);
        d2v = (double)v * (double)v;
    }
    double d1 = (double)v;

    double kls = 0.0;
    if (y == 1 && x == 0) {
        for (int idx = t; idx < B_ * L_; idx += 256) {
            double m  = (double)mu[idx];
            double lv = (double)logvar[idx];
            kls += 1.0 + lv - m * m - exp(lv);
        }
    }

#pragma unroll
    for (int o = 16; o > 0; o >>= 1) {
        d1  += __shfl_down_sync(0xffffffffu, d1,  o);
        d2v += __shfl_down_sync(0xffffffffu, d2v, o);
        kls += __shfl_down_sync(0xffffffffu, kls, o);
    }
    if ((t & 31) == 0) { s1s[t >> 5] = d1; s2s[t >> 5] = d2v; sks[t >> 5] = kls; }
    __syncthreads();

    if (t == 0) {
        double S1 = 0.0, S2 = 0.0, SK = 0.0;
#pragma unroll
        for (int w = 0; w < 8; w++) { S1 += s1s[w]; S2 += s2s[w]; SK += sks[w]; }
        if (y < 2) {
            atomicAdd(&g_acc[0], S1);
        } else {
            atomicAdd(&g_acc[1 + 2 * b], S1);
            atomicAdd(&g_acc[2 + 2 * b], S2);
        }
        if (y == 1 && x == 0) atomicAdd(&g_acc[5], SK);
        __threadfence();
        unsigned int n = atomicAdd(&g_count, 1u);
        last = (n == RTOT - 1);
    }
    __syncthreads();

    if (last && t == 0) {
        __threadfence();
        volatile double* acc = g_acc;
        double cd = acc[0] / (double)(B_ * N_);
        double dens = 0.0;
        for (int bb = 0; bb < B_; bb++) {
            double su  = acc[1 + 2 * bb];
            double su2 = acc[2 + 2 * bb];
            double var = (su2 - su * su / (double)N_) / (double)(N_ - 1);
            dens += sqrt(var > 0.0 ? var : 0.0);
        }
        dens /= (double)B_;
        double kl = -0.5 * acc[5] / (double)(B_ * L_);
        double total = cd + 0.001 * kl + 0.1 * dens;

        if (out_size > 0) out[0] = (float)total;
        if (out_size > 1) out[1] = (float)cd;
        if (out_size > 2) out[2] = (float)kl;
        if (out_size > 3) out[3] = (float)dens;

        // reset for next graph replay
        for (int k = 0; k < 6; k++) g_acc[k] = 0.0;
        __threadfence();
        g_count = 0u;
    }
}

extern "C" void kernel_launch(void* const* d_in, const int* in_sizes, int n_in,
                              void* d_out, int out_size) {
    const float* pred   = (const float*)d_in[0];
    const float* target = (const float*)d_in[1];
    const float* mu     = (const float*)d_in[2];
    const float* logvar = (const float*)d_in[3];
    float* out = (float*)d_out;

    pairmin_all<<<dim3(XBLKS, B_), TPB>>>(pred, target);
    reduce_final<<<dim3(32, 3), 256>>>(mu, logvar, out, out_size);
}

// round 14
// speedup vs baseline: 1.1967x; 1.0625x over previous
#include <cuda_runtime.h>
#include <cuda_bf16.h>
#include <math.h>

// Problem shape (fixed by reference setup_inputs)
#define B_    2
#define N_    4096
#define L_    512
#define TPB   128
#define KQ    4
#define KP    2
#define QC    512           // queries per block (KQ*TPB)
#define NQ    8             // query chunks
#define MCH   64            // m points per block
#define NMC   64            // m chunks
#define TILE  32            // m points per smem tile
#define NPH   2             // phases per block (MCH/TILE)
#define PTTP_BLKS (NQ*NMC)  // 512
#define PPS_BLKS  288       // upper-triangle (q,mc) pairs: sum_q (64-8q)
#define XBLKS     (PTTP_BLKS + PPS_BLKS)  // 800 -> 1600 blocks total
#define RTOT      96        // reduce blocks (32 x 3)
#define FINF 3.4e38f

// Scratch (allocation-free: __device__ globals)
__device__ float        g_rowPT[B_ * NMC * N_];  // 2 MB
__device__ float        g_colTP[B_ * NQ  * N_];
__device__ float        g_rowPP[B_ * NMC * N_];  // only mc >= 8*qc slots valid
__device__ float        g_colPP[B_ * NQ  * N_];  // only q <= qc slots valid
__device__ double       g_acc[6];    // [0]=PT+TP, [1,2]=PP s/s2 b0, [3,4]=b1, [5]=KL
__device__ unsigned int g_count;

// ---- f32x2 packed helpers -------------------------------------------------
static __device__ __forceinline__ unsigned long long pk2(float lo, float hi) {
    unsigned long long r;
    asm("mov.b64 %0, {%1,%2};" : "=l"(r) : "f"(lo), "f"(hi));
    return r;
}
static __device__ __forceinline__ unsigned long long fma2(
        unsigned long long a, unsigned long long b, unsigned long long c) {
    unsigned long long d;
    asm("fma.rn.f32x2 %0, %1, %2, %3;" : "=l"(d) : "l"(a), "l"(b), "l"(c));
    return d;
}
static __device__ __forceinline__ unsigned long long add2(
        unsigned long long a, unsigned long long b) {
    unsigned long long d;
    asm("add.rn.f32x2 %0, %1, %2;" : "=l"(d) : "l"(a), "l"(b));
    return d;
}
static __device__ __forceinline__ void upk2(unsigned long long v, float& lo, float& hi) {
    asm("mov.b64 {%0,%1}, %2;" : "=f"(lo), "=f"(hi) : "l"(v));
}

// ---- kernel 1: all pairwise-min work ---------------------------------------
// x < 512:  fused PT/TP block (q = x>>6 of pred, zc = x&63 m-chunk of target)
// x >= 512: PP upper-triangle block (q, mc) with mc >= 8q, self-masked on diag
// Col-min via REDUX.MIN.U32 per warp per j (d >= 0 -> uint order == float
// order), then a 4-way combine; replaces the serial per-phase scol fold.
__global__ void __launch_bounds__(TPB) pairmin_all(const float* __restrict__ pred,
                                                   const float* __restrict__ target) {
    __shared__ unsigned long long sd[TILE][4];
    __shared__ float scol2[TILE][5];   // [m][warp] cross-warp partials (+pad)

    const int t = threadIdx.x;
    const int b = blockIdx.y;
    const int x = blockIdx.x;
    const int w = t >> 5, lane = t & 31;

    const float* A; const float* P;
    float* rowdst; float* coldst;
    int q, mbase; bool selfpass;
    if (x < PTTP_BLKS) {
        q = x >> 6; const int zc = x & 63;
        mbase = zc * MCH;
        A = pred; P = target; selfpass = false;
        rowdst = g_rowPT + (size_t)(b * NMC + zc) * N_;
        coldst = g_colTP + (size_t)(b * NQ + q) * N_;
    } else {
        int s = x - PTTP_BLKS; q = 0; int cnt = NMC;
        while (s >= cnt) { s -= cnt; q++; cnt -= 8; }
        const int mc = 8 * q + s;
        mbase = mc * MCH;
        A = pred; P = pred; selfpass = true;
        rowdst = g_rowPP + (size_t)(b * NMC + mc) * N_;
        coldst = g_colPP + (size_t)(b * NQ + q) * N_;
    }
    const int qbase = q * QC;
    const int qi0   = qbase + t;

    unsigned long long px2[KP], py2[KP], pz2[KP], pp2[KP];
    float mn[KQ];
#pragma unroll
    for (int kp = 0; kp < KP; kp++) {
        const float* a0 = A + (size_t)(b * N_ + qi0 + (2 * kp)     * TPB) * 3;
        const float* a1 = A + (size_t)(b * N_ + qi0 + (2 * kp + 1) * TPB) * 3;
        float x0 = a0[0], y0 = a0[1], z0 = a0[2];
        float x1 = a1[0], y1 = a1[1], z1 = a1[2];
        px2[kp] = pk2(x0, x1); py2[kp] = pk2(y0, y1); pz2[kp] = pk2(z0, z1);
        pp2[kp] = pk2(fmaf(x0, x0, fmaf(y0, y0, z0 * z0)),
                      fmaf(x1, x1, fmaf(y1, y1, z1 * z1)));
        mn[2 * kp] = FINF; mn[2 * kp + 1] = FINF;
    }

#pragma unroll
    for (int ph = 0; ph < NPH; ph++) {
        const int m0 = mbase + ph * TILE;
        __syncthreads();
        if (t < TILE) {
            const float* p = P + (size_t)(b * N_ + m0 + t) * 3;
            float xx = p[0], yy = p[1], zz = p[2];
            sd[t][0] = pk2(-2.f * xx, -2.f * xx);
            sd[t][1] = pk2(-2.f * yy, -2.f * yy);
            sd[t][2] = pk2(-2.f * zz, -2.f * zz);
            float ss = fmaf(xx, xx, fmaf(yy, yy, zz * zz));
            sd[t][3] = pk2(ss, ss);
        }
        __syncthreads();

        const bool dg = selfpass && (m0 < qbase + QC) && (m0 + TILE > qbase);
        if (!dg) {
#pragma unroll 8
            for (int j = 0; j < TILE; j++) {
                const ulonglong2 v01 = *reinterpret_cast<const ulonglong2*>(&sd[j][0]);
                const ulonglong2 v23 = *reinterpret_cast<const ulonglong2*>(&sd[j][2]);
                float cm = FINF;
#pragma unroll
                for (int kp = 0; kp < KP; kp++) {
                    unsigned long long e = add2(v23.y, pp2[kp]);   // ss + pp
                    e = fma2(pz2[kp], v23.x, e);
                    e = fma2(py2[kp], v01.y, e);
                    e = fma2(px2[kp], v01.x, e);                   // = packed d
                    float d0, d1; upk2(e, d0, d1);
                    mn[2 * kp]     = fminf(mn[2 * kp],     d0);
                    mn[2 * kp + 1] = fminf(mn[2 * kp + 1], d1);
                    cm = fminf(cm, fminf(d0, d1));
                }
                unsigned int cu = __reduce_min_sync(0xffffffffu, __float_as_uint(cm));
                if (lane == 0) scol2[j][w] = __uint_as_float(cu);
            }
        } else {
#pragma unroll 4
            for (int j = 0; j < TILE; j++) {
                const ulonglong2 v01 = *reinterpret_cast<const ulonglong2*>(&sd[j][0]);
                const ulonglong2 v23 = *reinterpret_cast<const ulonglong2*>(&sd[j][2]);
                const int m = m0 + j;
                float cm = FINF;
#pragma unroll
                for (int kp = 0; kp < KP; kp++) {
                    unsigned long long e = add2(v23.y, pp2[kp]);
                    e = fma2(pz2[kp], v23.x, e);
                    e = fma2(py2[kp], v01.y, e);
                    e = fma2(px2[kp], v01.x, e);
                    float d0, d1; upk2(e, d0, d1);
                    if (m == qi0 + (2 * kp)     * TPB) d0 = FINF;  // self mask
                    if (m == qi0 + (2 * kp + 1) * TPB) d1 = FINF;
                    mn[2 * kp]     = fminf(mn[2 * kp],     d0);
                    mn[2 * kp + 1] = fminf(mn[2 * kp + 1], d1);
                    cm = fminf(cm, fminf(d0, d1));
                }
                unsigned int cu = __reduce_min_sync(0xffffffffu, __float_as_uint(cm));
                if (lane == 0) scol2[j][w] = __uint_as_float(cu);
            }
        }
        __syncthreads();

        // tiny fold: 32 threads combine 4 warp partials per m
        if (t < TILE) {
            float v = fminf(fminf(scol2[t][0], scol2[t][1]),
                            fminf(scol2[t][2], scol2[t][3]));
            coldst[m0 + t] = v;
        }
    }

#pragma unroll
    for (int k = 0; k < KQ; k++) rowdst[qi0 + k * TPB] = mn[k];
}

// ---- kernel 2: reduce + KL + finalize (counter pattern, self-resetting) ----
// grid (32, 3): y=0 PT rows (depth 64), y=1 TP cols (depth 8) + KL in x==0,
// y=2 PP (rows mc in [8qc,64) + cols q in [0,qc]), qc = i>>9.
__global__ void __launch_bounds__(256) reduce_final(const float* __restrict__ mu,
                                                    const float* __restrict__ logvar,
                                                    float* __restrict__ out,
                                                    int out_size) {
    __shared__ double s1s[8], s2s[8], sks[8];
    __shared__ bool last;

    const int t = threadIdx.x, x = blockIdx.x, y = blockIdx.y;
    const int g = x * 256 + t;
    const int b = g >> 12;
    const int i = g & (N_ - 1);

    float v = FINF;
    double d2v = 0.0;
    if (y == 0) {
        const float* p = g_rowPT + (size_t)b * NMC * N_ + i;
#pragma unroll
        for (int s = 0; s < NMC; s++) v = fminf(v, p[(size_t)s * N_]);
    } else if (y == 1) {
        const float* p = g_colTP + (size_t)b * NQ * N_ + i;
#pragma unroll
        for (int s = 0; s < NQ; s++) v = fminf(v, p[(size_t)s * N_]);
    } else {
        const int qc = i >> 9;   // uniform within block (256-aligned chunks)
        const float* pr = g_rowPP + (size_t)b * NMC * N_ + i;
        for (int mc = 8 * qc; mc < NMC; mc++) v = fminf(v, pr[(size_t)mc * N_]);
        const float* pc = g_colPP + (size_t)b * NQ * N_ + i;
        for (int qq = 0; qq <= qc; qq++) v = fminf(v, pc[(size_t)qq * N_]);
        d2v = (double)v * (double)v;
    }
    double d1 = (double)v;

    double kls = 0.0;
    if (y == 1 && x == 0) {
        for (int idx = t; idx < B_ * L_; idx += 256) {
            double m  = (double)mu[idx];
            double lv = (double)logvar[idx];
            kls += 1.0 + lv - m * m - exp(lv);
        }
    }

#pragma unroll
    for (int o = 16; o > 0; o >>= 1) {
        d1  += __shfl_down_sync(0xffffffffu, d1,  o);
        d2v += __shfl_down_sync(0xffffffffu, d2v, o);
        kls += __shfl_down_sync(0xffffffffu, kls, o);
    }
    if ((t & 31) == 0) { s1s[t >> 5] = d1; s2s[t >> 5] = d2v; sks[t >> 5] = kls; }
    __syncthreads();

    if (t == 0) {
        double S1 = 0.0, S2 = 0.0, SK = 0.0;
#pragma unroll
        for (int w = 0; w < 8; w++) { S1 += s1s[w]; S2 += s2s[w]; SK += sks[w]; }
        if (y < 2) {
            atomicAdd(&g_acc[0], S1);
        } else {
            atomicAdd(&g_acc[1 + 2 * b], S1);
            atomicAdd(&g_acc[2 + 2 * b], S2);
        }
        if (y == 1 && x == 0) atomicAdd(&g_acc[5], SK);
        __threadfence();
        unsigned int n = atomicAdd(&g_count, 1u);
        last = (n == RTOT - 1);
    }
    __syncthreads();

    if (last && t == 0) {
        __threadfence();
        volatile double* acc = g_acc;
        double cd = acc[0] / (double)(B_ * N_);
        double dens = 0.0;
        for (int bb = 0; bb < B_; bb++) {
            double su  = acc[1 + 2 * bb];
            double su2 = acc[2 + 2 * bb];
            double var = (su2 - su * su / (double)N_) / (double)(N_ - 1);
            dens += sqrt(var > 0.0 ? var : 0.0);
        }
        dens /= (double)B_;
        double kl = -0.5 * acc[5] / (double)(B_ * L_);
        double total = cd + 0.001 * kl + 0.1 * dens;

        if (out_size > 0) out[0] = (float)total;
        if (out_size > 1) out[1] = (float)cd;
        if (out_size > 2) out[2] = (float)kl;
        if (out_size > 3) out[3] = (float)dens;

        // reset for next graph replay
        for (int k = 0; k < 6; k++) g_acc[k] = 0.0;
        __threadfence();
        g_count = 0u;
    }
}

extern "C" void kernel_launch(void* const* d_in, const int* in_sizes, int n_in,
                              void* d_out, int out_size) {
    const float* pred   = (const float*)d_in[0];
    const float* target = (const float*)d_in[1];
    const float* mu     = (const float*)d_in[2];
    const float* logvar = (const float*)d_in[3];
    float* out = (float*)d_out;

    pairmin_all<<<dim3(XBLKS, B_), TPB>>>(pred, target);
    reduce_final<<<dim3(32, 3), 256>>>(mu, logvar, out, out_size);
}